// round 11
// baseline (speedup 1.0000x reference)
#include <cuda_runtime.h>
#include <cuda_bf16.h>
#include <math.h>
#include <stdint.h>

#define NB    8
#define HH    32
#define WW    32
#define CINC  256
#define NHEAD 8
#define SEQ   1024

// ---------------- scratch (static device globals; no allocation) ----------------
__device__ float g_q[NB*NHEAD*SEQ*8];
__device__ float g_k[NB*NHEAD*SEQ*8];
__device__ float g_v[NB*NHEAD*SEQ*8];
__device__ float g_attn[NB*SEQ*64];

// split-bf16 transposed weights: conv B (192 x 2304), qkv B (192 x 256)
__device__ __align__(16) __nv_bfloat16 g_Bhi[192*2304];
__device__ __align__(16) __nv_bfloat16 g_Blo[192*2304];
__device__ __align__(16) __nv_bfloat16 g_QBhi[192*256];
__device__ __align__(16) __nv_bfloat16 g_QBlo[192*256];

__device__ __forceinline__ float ex2f(float x) {
    float y;
    asm("ex2.approx.f32 %0, %1;" : "=f"(y) : "f"(x));
    return y;
}

// ================= warp-level bf16 MMA (sm_80+ PTX; works on plain compute_103) ====
__device__ __forceinline__ void mma_bf16(float* c, const uint32_t* a, const uint32_t* b)
{
    asm volatile(
        "mma.sync.aligned.m16n8k16.row.col.f32.bf16.bf16.f32 "
        "{%0,%1,%2,%3}, {%4,%5,%6,%7}, {%8,%9}, {%0,%1,%2,%3};\n"
        : "+f"(c[0]), "+f"(c[1]), "+f"(c[2]), "+f"(c[3])
        : "r"(a[0]), "r"(a[1]), "r"(a[2]), "r"(a[3]),
          "r"(b[0]), "r"(b[1]));
}

// ================= weight prep: transpose + hi/lo split =================
__global__ __launch_bounds__(256) void bprep_kernel(
    const float* __restrict__ conv_w, const float* __restrict__ qkv_w)
{
    int idx = blockIdx.x * 256 + threadIdx.x;
    if (idx < 192*2304) {
        int n = idx / 2304, k = idx - n*2304;
        float v = conv_w[k*192 + n];
        __nv_bfloat16 h = __float2bfloat16(v);
        g_Bhi[idx] = h;
        g_Blo[idx] = __float2bfloat16(v - __bfloat162float(h));
    } else {
        int j = idx - 192*2304;
        if (j < 192*256) {
            int n = j / 256, k = j - n*256;
            float v = qkv_w[k*192 + n];
            __nv_bfloat16 h = __float2bfloat16(v);
            g_QBhi[j] = h;
            g_QBlo[j] = __float2bfloat16(v - __bfloat162float(h));
        }
    }
}

// ================= qkv scatter helper =================
__device__ __forceinline__ void qkv_store(int row, int col, float v, const float* bias)
{
    v += bias[col];
    int b = row >> 10, s = row & 1023;
    if (col < 64) {
        g_k[((b*8 + (col >> 3))*SEQ + s)*8 + (col & 7)] = v;
    } else if (col < 128) {
        int o = col - 64;
        g_q[((b*8 + (o >> 3))*SEQ + s)*8 + (o & 7)] = v * 0.35355339059327373f;
    } else {
        int o = col - 128;
        g_v[((b*8 + (o >> 3))*SEQ + s)*8 + (o & 7)] = v;
    }
}

// ================= unified split-bf16 GEMM (MODE 0 = conv-im2col, MODE 1 = qkv) =====
#define STG_ELEMS 20480
#define GEMM_SMEM (2*STG_ELEMS*2)

template<int MODE>
__global__ __launch_bounds__(256, 1) void gemm_kernel(
    const float* __restrict__ x,
    const __nv_bfloat16* __restrict__ Bhi,
    const __nv_bfloat16* __restrict__ Blo,
    const float* __restrict__ bias,
    float* __restrict__ out)
{
    constexpr int NC = MODE ? 8 : 72;
    constexpr int KB = MODE ? 256 : 2304;

    extern __shared__ __align__(16) __nv_bfloat16 sm[];

    const int tid  = threadIdx.x;
    const int lane = tid & 31;
    const int wid  = tid >> 5;
    const int mt   = blockIdx.x;

    const int ar  = tid >> 2;
    const int acg = (tid & 3) * 8;
    const int p   = mt*64 + ar;
    const int pb  = p >> 10, py = (p >> 5) & 31, px = p & 31;

    float aregs[8];
    uint4 bregs[6];

    const int wm = (wid >> 2) * 32;
    const int wn = (wid & 3) * 48;
    const int g  = lane >> 2;
    const int tg = lane & 3;

    float acc[2][6][4];
    #pragma unroll
    for (int mi = 0; mi < 2; mi++)
        #pragma unroll
        for (int ni = 0; ni < 6; ni++)
            #pragma unroll
            for (int e = 0; e < 4; e++) acc[mi][ni][e] = 0.f;

    auto ldgA = [&](int kc) {
        int dy, dx, c0;
        if (MODE) { dy = 0; dx = 0; c0 = kc * 32; }
        else { int t = kc >> 3; dy = t/3 - 1; dx = t%3 - 1; c0 = (kc & 7) * 32; }
        int yy = py + dy, xx = px + dx;
        bool valid = MODE ? true : ((unsigned)yy < 32u && (unsigned)xx < 32u);
        if (valid) {
            const float4* s = reinterpret_cast<const float4*>(
                x + ((size_t)(pb*1024 + yy*32 + xx))*256 + c0 + acg);
            float4 v0 = s[0], v1 = s[1];
            aregs[0]=v0.x; aregs[1]=v0.y; aregs[2]=v0.z; aregs[3]=v0.w;
            aregs[4]=v1.x; aregs[5]=v1.y; aregs[6]=v1.z; aregs[7]=v1.w;
        } else {
            #pragma unroll
            for (int i = 0; i < 8; i++) aregs[i] = 0.f;
        }
    };

    auto ldgB = [&](int kc) {
        const int kbase = kc * 32;
        #pragma unroll
        for (int i = 0; i < 6; i++) {
            int idx  = tid + i*256;
            int half = idx >= 768;
            int j    = idx - half*768;
            int n    = j >> 2, gg = (j & 3) * 8;
            const __nv_bfloat16* src = (half ? Blo : Bhi) + (size_t)n*KB + kbase + gg;
            bregs[i] = *reinterpret_cast<const uint4*>(src);
        }
    };

    auto stsA = [&](int st) {
        __nv_bfloat16* As = sm + st*STG_ELEMS;
        __nv_bfloat162 h[4], l[4];
        #pragma unroll
        for (int i = 0; i < 4; i++) {
            float v0 = aregs[2*i], v1 = aregs[2*i+1];
            __nv_bfloat16 h0 = __float2bfloat16(v0), h1 = __float2bfloat16(v1);
            h[i].x = h0; h[i].y = h1;
            l[i].x = __float2bfloat16(v0 - __bfloat162float(h0));
            l[i].y = __float2bfloat16(v1 - __bfloat162float(h1));
        }
        *reinterpret_cast<uint4*>(As + ar*40 + acg)        = *reinterpret_cast<uint4*>(h);
        *reinterpret_cast<uint4*>(As + 2560 + ar*40 + acg) = *reinterpret_cast<uint4*>(l);
    };

    auto stsB = [&](int st) {
        __nv_bfloat16* Bs = sm + st*STG_ELEMS + 5120;
        #pragma unroll
        for (int i = 0; i < 6; i++) {
            int idx  = tid + i*256;
            int half = idx >= 768;
            int j    = idx - half*768;
            int n    = j >> 2, gg = (j & 3) * 8;
            *reinterpret_cast<uint4*>(Bs + half*7680 + n*40 + gg) = bregs[i];
        }
    };

    auto compute = [&](int st) {
        const uint32_t* As = reinterpret_cast<const uint32_t*>(sm + st*STG_ELEMS);
        const uint32_t* Bs = reinterpret_cast<const uint32_t*>(sm + st*STG_ELEMS + 5120);
        #pragma unroll
        for (int ks = 0; ks < 2; ks++) {
            const int k0 = ks * 8;
            uint32_t ahi[2][4], alo[2][4];
            #pragma unroll
            for (int mi = 0; mi < 2; mi++) {
                int base = (wm + mi*16 + g)*20 + k0 + tg;
                ahi[mi][0] = As[base];        ahi[mi][1] = As[base + 160];
                ahi[mi][2] = As[base + 4];    ahi[mi][3] = As[base + 164];
                alo[mi][0] = As[1280 + base];       alo[mi][1] = As[1280 + base + 160];
                alo[mi][2] = As[1280 + base + 4];   alo[mi][3] = As[1280 + base + 164];
            }
            uint32_t bhi[6][2], blo[6][2];
            #pragma unroll
            for (int ni = 0; ni < 6; ni++) {
                int base = (wn + ni*8 + g)*20 + k0 + tg;
                bhi[ni][0] = Bs[base];        bhi[ni][1] = Bs[base + 4];
                blo[ni][0] = Bs[3840 + base]; blo[ni][1] = Bs[3840 + base + 4];
            }
            #pragma unroll
            for (int mi = 0; mi < 2; mi++)
                #pragma unroll
                for (int ni = 0; ni < 6; ni++) {
                    mma_bf16(acc[mi][ni], ahi[mi], bhi[ni]);
                    mma_bf16(acc[mi][ni], ahi[mi], blo[ni]);
                    mma_bf16(acc[mi][ni], alo[mi], bhi[ni]);
                }
        }
    };

    ldgA(0); ldgB(0); stsA(0); stsB(0);
    for (int kc = 0; kc < NC; kc++) {
        if (kc + 1 < NC) { ldgA(kc+1); ldgB(kc+1); }
        __syncthreads();
        compute(kc & 1);
        if (kc + 1 < NC) { stsA((kc+1) & 1); stsB((kc+1) & 1); }
    }

    if (MODE == 0) {
        #pragma unroll
        for (int mi = 0; mi < 2; mi++)
            #pragma unroll
            for (int ni = 0; ni < 6; ni++) {
                int col  = wn + ni*8 + tg*2;
                int row0 = mt*64 + wm + mi*16 + g;
                float b0 = bias[col], b1 = bias[col+1];
                float2 v0 = make_float2(acc[mi][ni][0] + b0, acc[mi][ni][1] + b1);
                float2 v1 = make_float2(acc[mi][ni][2] + b0, acc[mi][ni][3] + b1);
                *reinterpret_cast<float2*>(out + (size_t)row0*256 + col)     = v0;
                *reinterpret_cast<float2*>(out + (size_t)(row0+8)*256 + col) = v1;
            }
    } else {
        #pragma unroll
        for (int mi = 0; mi < 2; mi++)
            #pragma unroll
            for (int ni = 0; ni < 6; ni++) {
                int col = wn + ni*8 + tg*2;
                int row = mt*64 + wm + mi*16 + g;
                qkv_store(row,     col,     acc[mi][ni][0], bias);
                qkv_store(row,     col + 1, acc[mi][ni][1], bias);
                qkv_store(row + 8, col,     acc[mi][ni][2], bias);
                qkv_store(row + 8, col + 1, acc[mi][ni][3], bias);
            }
    }
}

// ================= fused attention v2: online softmax + vector LDS =================
// block = (b, n, xi): 32 queries x 1024 keys. Warp w owns queries yq in [4w,4w+4),
// lane l owns keys j = t*32 + l. Everything exp-related is in log2 domain
// (q pre-scaled by log2 e), single pass, per-lane online max, butterfly merge.
// smem: K0/K1/V0/V1 float4[1024] each (conflict-free LDS.128), rw/rh 32x32, qs 256.
#define ATTN_SMEM ((4*4096 + 1024 + 1024 + 256) * 4)

__global__ __launch_bounds__(256, 2) void attn_kernel(
    const float* __restrict__ rel_w, const float* __restrict__ rel_h)
{
    extern __shared__ float smf[];
    float4* K0 = reinterpret_cast<float4*>(smf);
    float4* K1 = reinterpret_cast<float4*>(smf + 4096);
    float4* V0 = reinterpret_cast<float4*>(smf + 8192);
    float4* V1 = reinterpret_cast<float4*>(smf + 12288);
    float*  rw = smf + 16384;
    float*  rh = smf + 17408;
    float*  qs = smf + 18432;

    const int tid  = threadIdx.x;
    const int lane = tid & 31;
    const int wrp  = tid >> 5;
    const int blk  = blockIdx.x;
    const int bn   = blk >> 5;
    const int xi   = blk & 31;

    const float4* kg = reinterpret_cast<const float4*>(g_k + bn*SEQ*8);
    const float4* vg = reinterpret_cast<const float4*>(g_v + bn*SEQ*8);
    const float*  qg = g_q + bn*SEQ*8 + xi*32*8;

    // K/V: coalesced LDG.128, scatter into half-arrays
    for (int i = tid; i < 2048; i += 256) {
        float4 kv = kg[i];
        float4 vv = vg[i];
        int j = i >> 1;
        if (i & 1) { K1[j] = kv; V1[j] = vv; }
        else       { K0[j] = kv; V0[j] = vv; }
    }
    qs[tid] = qg[tid] * 1.4426950408889634f;   // log2(e) — all logits in log2 units
    __syncthreads();

    for (int e = tid; e < 1024; e += 256) {
        int yq = e >> 5, yj = e & 31;
        const float* rk = rel_w + (yj - yq + 31)*8;
        float s = 0.f;
        #pragma unroll
        for (int d = 0; d < 8; d++) s = fmaf(qs[yq*8 + d], rk[d], s);
        rw[e] = s;
    }
    for (int e = tid; e < 1024; e += 256) {
        int yq = e >> 5, xj = e & 31;
        const float* rk = rel_h + (xj - xi + 31)*8;
        float s = 0.f;
        #pragma unroll
        for (int d = 0; d < 8; d++) s = fmaf(qs[yq*8 + d], rk[d], s);
        rh[e] = s;
    }
    __syncthreads();

    const int w4 = wrp * 4;
    float qv[4][8];
    float rwd[4];
    #pragma unroll
    for (int qi = 0; qi < 4; qi++) {
        rwd[qi] = rw[(w4 + qi)*32 + lane];
        #pragma unroll
        for (int d = 0; d < 8; d++) qv[qi][d] = qs[(w4 + qi)*8 + d];
    }

    float m[4]    = {-1e30f, -1e30f, -1e30f, -1e30f};
    float ssum[4] = {0.f, 0.f, 0.f, 0.f};
    float acc[4][8];
    #pragma unroll
    for (int qi = 0; qi < 4; qi++)
        #pragma unroll
        for (int d = 0; d < 8; d++) acc[qi][d] = 0.f;

    // single pass: online per-lane softmax (log2 domain)
    for (int t = 0; t < 32; t++) {
        const int j = t*32 + lane;
        const float4 k0 = K0[j], k1 = K1[j];
        const float4 v0 = V0[j], v1 = V1[j];
        #pragma unroll
        for (int qi = 0; qi < 4; qi++) {
            float lg = rwd[qi] + rh[(w4 + qi)*32 + t];
            lg = fmaf(qv[qi][0], k0.x, lg);
            lg = fmaf(qv[qi][1], k0.y, lg);
            lg = fmaf(qv[qi][2], k0.z, lg);
            lg = fmaf(qv[qi][3], k0.w, lg);
            lg = fmaf(qv[qi][4], k1.x, lg);
            lg = fmaf(qv[qi][5], k1.y, lg);
            lg = fmaf(qv[qi][6], k1.z, lg);
            lg = fmaf(qv[qi][7], k1.w, lg);
            if (lg > m[qi]) {                     // rare: rescale history
                float sc = ex2f(m[qi] - lg);
                ssum[qi] *= sc;
                #pragma unroll
                for (int d = 0; d < 8; d++) acc[qi][d] *= sc;
                m[qi] = lg;
            }
            float p = ex2f(lg - m[qi]);
            ssum[qi] += p;
            acc[qi][0] = fmaf(p, v0.x, acc[qi][0]);
            acc[qi][1] = fmaf(p, v0.y, acc[qi][1]);
            acc[qi][2] = fmaf(p, v0.z, acc[qi][2]);
            acc[qi][3] = fmaf(p, v0.w, acc[qi][3]);
            acc[qi][4] = fmaf(p, v1.x, acc[qi][4]);
            acc[qi][5] = fmaf(p, v1.y, acc[qi][5]);
            acc[qi][6] = fmaf(p, v1.z, acc[qi][6]);
            acc[qi][7] = fmaf(p, v1.w, acc[qi][7]);
        }
    }

    // butterfly allreduce with max-rescale
    #pragma unroll
    for (int off = 16; off > 0; off >>= 1) {
        #pragma unroll
        for (int qi = 0; qi < 4; qi++) {
            float om = __shfl_xor_sync(0xffffffffu, m[qi], off);
            float os = __shfl_xor_sync(0xffffffffu, ssum[qi], off);
            float nm = fmaxf(m[qi], om);
            float s1 = ex2f(m[qi] - nm);
            float s2 = ex2f(om - nm);
            ssum[qi] = ssum[qi]*s1 + os*s2;
            #pragma unroll
            for (int d = 0; d < 8; d++) {
                float oa = __shfl_xor_sync(0xffffffffu, acc[qi][d], off);
                acc[qi][d] = acc[qi][d]*s1 + oa*s2;
            }
            m[qi] = nm;
        }
    }

    __syncthreads();   // qs/rw reads done everywhere; reuse qs as staging
    if (lane == 0) {
        #pragma unroll
        for (int qi = 0; qi < 4; qi++) {
            float inv = 1.f / ssum[qi];
            #pragma unroll
            for (int d = 0; d < 8; d++) qs[(w4 + qi)*8 + d] = acc[qi][d] * inv;
        }
    }
    __syncthreads();
    {
        int b = bn >> 3, n = bn & 7;
        int yq = tid >> 3, d = tid & 7;
        g_attn[(b*SEQ + xi*32 + yq)*64 + n*8 + d] = qs[tid];
    }
}

// ================= output projection =================
__global__ __launch_bounds__(256) void proj_kernel(
    const float* __restrict__ w, const float* __restrict__ bias,
    float* __restrict__ out)
{
    __shared__ float at[32][64];
    __shared__ float ws[64][64];
    const int tid = threadIdx.x;
    const int p0  = blockIdx.x * 32;

    for (int i = tid; i < 32*64; i += 256) at[i >> 6][i & 63] = g_attn[p0*64 + i];
    for (int i = tid; i < 64*64; i += 256) ws[i >> 6][i & 63] = w[i];
    __syncthreads();

    const int o  = tid & 63;
    const int pg = tid >> 6;
    float acc[8];
    #pragma unroll
    for (int i = 0; i < 8; i++) acc[i] = 0.f;

    #pragma unroll
    for (int c = 0; c < 64; c++) {
        float wv = ws[c][o];
        #pragma unroll
        for (int i = 0; i < 8; i++)
            acc[i] = fmaf(at[pg + 4*i][c], wv, acc[i]);
    }
    float bb = bias[o];
    #pragma unroll
    for (int i = 0; i < 8; i++)
        out[(p0 + pg + 4*i)*256 + 192 + o] = acc[i] + bb;
}

// ================= launch =================
extern "C" void kernel_launch(void* const* d_in, const int* in_sizes, int n_in,
                              void* d_out, int out_size)
{
    const float* x       = (const float*)d_in[0];
    const float* conv_w  = (const float*)d_in[1];
    const float* conv_b  = (const float*)d_in[2];
    const float* qkv_w   = (const float*)d_in[3];
    const float* qkv_b   = (const float*)d_in[4];
    const float* attn_w  = (const float*)d_in[5];
    const float* attn_b  = (const float*)d_in[6];
    const float* relw    = (const float*)d_in[7];
    const float* relh    = (const float*)d_in[8];
    float* out = (float*)d_out;

    __nv_bfloat16 *bhi, *blo, *qbhi, *qblo;
    cudaGetSymbolAddress((void**)&bhi,  g_Bhi);
    cudaGetSymbolAddress((void**)&blo,  g_Blo);
    cudaGetSymbolAddress((void**)&qbhi, g_QBhi);
    cudaGetSymbolAddress((void**)&qblo, g_QBlo);

    cudaFuncSetAttribute(attn_kernel, cudaFuncAttributeMaxDynamicSharedMemorySize, ATTN_SMEM);
    cudaFuncSetAttribute(gemm_kernel<0>, cudaFuncAttributeMaxDynamicSharedMemorySize, GEMM_SMEM);
    cudaFuncSetAttribute(gemm_kernel<1>, cudaFuncAttributeMaxDynamicSharedMemorySize, GEMM_SMEM);

    bprep_kernel<<<(192*2304 + 192*256 + 255)/256, 256>>>(conv_w, qkv_w);
    gemm_kernel<1><<<128, 256, GEMM_SMEM>>>(x, qbhi, qblo, qkv_b, nullptr);
    gemm_kernel<0><<<128, 256, GEMM_SMEM>>>(x, bhi, blo, conv_b, out);
    attn_kernel<<<NB*NHEAD*HH, 256, ATTN_SMEM>>>(relw, relh);
    proj_kernel<<<NB*SEQ/32, 256>>>(attn_w, attn_b, out);
}

// round 16
// speedup vs baseline: 1.0969x; 1.0969x over previous
#include <cuda_runtime.h>
#include <cuda_bf16.h>
#include <math.h>
#include <stdint.h>

#define NB    8
#define HH    32
#define WW    32
#define CINC  256
#define NHEAD 8
#define SEQ   1024

// ---------------- scratch (static device globals; no allocation) ----------------
__device__ float g_q[NB*NHEAD*SEQ*8];
__device__ float g_k[NB*NHEAD*SEQ*8];
__device__ float g_v[NB*NHEAD*SEQ*8];
__device__ float g_attn[NB*SEQ*64];

// split-bf16 transposed weights: conv B (192 x 2304), qkv B (192 x 256)
__device__ __align__(16) __nv_bfloat16 g_Bhi[192*2304];
__device__ __align__(16) __nv_bfloat16 g_Blo[192*2304];
__device__ __align__(16) __nv_bfloat16 g_QBhi[192*256];
__device__ __align__(16) __nv_bfloat16 g_QBlo[192*256];

__device__ __forceinline__ float ex2f(float x) {
    float y;
    asm("ex2.approx.f32 %0, %1;" : "=f"(y) : "f"(x));
    return y;
}

// ================= warp-level bf16 MMA (sm_80+ PTX; works on plain compute_103) ====
__device__ __forceinline__ void mma_bf16(float* c, const uint32_t* a, const uint32_t* b)
{
    asm volatile(
        "mma.sync.aligned.m16n8k16.row.col.f32.bf16.bf16.f32 "
        "{%0,%1,%2,%3}, {%4,%5,%6,%7}, {%8,%9}, {%0,%1,%2,%3};\n"
        : "+f"(c[0]), "+f"(c[1]), "+f"(c[2]), "+f"(c[3])
        : "r"(a[0]), "r"(a[1]), "r"(a[2]), "r"(a[3]),
          "r"(b[0]), "r"(b[1]));
}

// ================= weight prep: transpose + hi/lo split =================
__global__ __launch_bounds__(256) void bprep_kernel(
    const float* __restrict__ conv_w, const float* __restrict__ qkv_w)
{
    int idx = blockIdx.x * 256 + threadIdx.x;
    if (idx < 192*2304) {
        int n = idx / 2304, k = idx - n*2304;
        float v = conv_w[k*192 + n];
        __nv_bfloat16 h = __float2bfloat16(v);
        g_Bhi[idx] = h;
        g_Blo[idx] = __float2bfloat16(v - __bfloat162float(h));
    } else {
        int j = idx - 192*2304;
        if (j < 192*256) {
            int n = j / 256, k = j - n*256;
            float v = qkv_w[k*192 + n];
            __nv_bfloat16 h = __float2bfloat16(v);
            g_QBhi[j] = h;
            g_QBlo[j] = __float2bfloat16(v - __bfloat162float(h));
        }
    }
}

// ================= qkv scatter helper =================
__device__ __forceinline__ void qkv_store(int row, int col, float v, const float* bias)
{
    v += bias[col];
    int b = row >> 10, s = row & 1023;
    if (col < 64) {
        g_k[((b*8 + (col >> 3))*SEQ + s)*8 + (col & 7)] = v;
    } else if (col < 128) {
        int o = col - 64;
        g_q[((b*8 + (o >> 3))*SEQ + s)*8 + (o & 7)] = v * 0.35355339059327373f;
    } else {
        int o = col - 128;
        g_v[((b*8 + (o >> 3))*SEQ + s)*8 + (o & 7)] = v;
    }
}

// ================= unified split-bf16 GEMM (MODE 0 = conv-im2col, MODE 1 = qkv) =====
#define STG_ELEMS 20480
#define GEMM_SMEM (2*STG_ELEMS*2)

template<int MODE>
__global__ __launch_bounds__(256, 1) void gemm_kernel(
    const float* __restrict__ x,
    const __nv_bfloat16* __restrict__ Bhi,
    const __nv_bfloat16* __restrict__ Blo,
    const float* __restrict__ bias,
    float* __restrict__ out)
{
    constexpr int NC = MODE ? 8 : 72;
    constexpr int KB = MODE ? 256 : 2304;

    extern __shared__ __align__(16) __nv_bfloat16 sm[];

    const int tid  = threadIdx.x;
    const int lane = tid & 31;
    const int wid  = tid >> 5;
    const int mt   = blockIdx.x;

    const int ar  = tid >> 2;
    const int acg = (tid & 3) * 8;
    const int p   = mt*64 + ar;
    const int pb  = p >> 10, py = (p >> 5) & 31, px = p & 31;

    float aregs[8];
    uint4 bregs[6];

    const int wm = (wid >> 2) * 32;
    const int wn = (wid & 3) * 48;
    const int g  = lane >> 2;
    const int tg = lane & 3;

    float acc[2][6][4];
    #pragma unroll
    for (int mi = 0; mi < 2; mi++)
        #pragma unroll
        for (int ni = 0; ni < 6; ni++)
            #pragma unroll
            for (int e = 0; e < 4; e++) acc[mi][ni][e] = 0.f;

    auto ldgA = [&](int kc) {
        int dy, dx, c0;
        if (MODE) { dy = 0; dx = 0; c0 = kc * 32; }
        else { int t = kc >> 3; dy = t/3 - 1; dx = t%3 - 1; c0 = (kc & 7) * 32; }
        int yy = py + dy, xx = px + dx;
        bool valid = MODE ? true : ((unsigned)yy < 32u && (unsigned)xx < 32u);
        if (valid) {
            const float4* s = reinterpret_cast<const float4*>(
                x + ((size_t)(pb*1024 + yy*32 + xx))*256 + c0 + acg);
            float4 v0 = s[0], v1 = s[1];
            aregs[0]=v0.x; aregs[1]=v0.y; aregs[2]=v0.z; aregs[3]=v0.w;
            aregs[4]=v1.x; aregs[5]=v1.y; aregs[6]=v1.z; aregs[7]=v1.w;
        } else {
            #pragma unroll
            for (int i = 0; i < 8; i++) aregs[i] = 0.f;
        }
    };

    auto ldgB = [&](int kc) {
        const int kbase = kc * 32;
        #pragma unroll
        for (int i = 0; i < 6; i++) {
            int idx  = tid + i*256;
            int half = idx >= 768;
            int j    = idx - half*768;
            int n    = j >> 2, gg = (j & 3) * 8;
            const __nv_bfloat16* src = (half ? Blo : Bhi) + (size_t)n*KB + kbase + gg;
            bregs[i] = *reinterpret_cast<const uint4*>(src);
        }
    };

    auto stsA = [&](int st) {
        __nv_bfloat16* As = sm + st*STG_ELEMS;
        __nv_bfloat162 h[4], l[4];
        #pragma unroll
        for (int i = 0; i < 4; i++) {
            float v0 = aregs[2*i], v1 = aregs[2*i+1];
            __nv_bfloat16 h0 = __float2bfloat16(v0), h1 = __float2bfloat16(v1);
            h[i].x = h0; h[i].y = h1;
            l[i].x = __float2bfloat16(v0 - __bfloat162float(h0));
            l[i].y = __float2bfloat16(v1 - __bfloat162float(h1));
        }
        *reinterpret_cast<uint4*>(As + ar*40 + acg)        = *reinterpret_cast<uint4*>(h);
        *reinterpret_cast<uint4*>(As + 2560 + ar*40 + acg) = *reinterpret_cast<uint4*>(l);
    };

    auto stsB = [&](int st) {
        __nv_bfloat16* Bs = sm + st*STG_ELEMS + 5120;
        #pragma unroll
        for (int i = 0; i < 6; i++) {
            int idx  = tid + i*256;
            int half = idx >= 768;
            int j    = idx - half*768;
            int n    = j >> 2, gg = (j & 3) * 8;
            *reinterpret_cast<uint4*>(Bs + half*7680 + n*40 + gg) = bregs[i];
        }
    };

    auto compute = [&](int st) {
        const uint32_t* As = reinterpret_cast<const uint32_t*>(sm + st*STG_ELEMS);
        const uint32_t* Bs = reinterpret_cast<const uint32_t*>(sm + st*STG_ELEMS + 5120);
        #pragma unroll
        for (int ks = 0; ks < 2; ks++) {
            const int k0 = ks * 8;
            uint32_t ahi[2][4], alo[2][4];
            #pragma unroll
            for (int mi = 0; mi < 2; mi++) {
                int base = (wm + mi*16 + g)*20 + k0 + tg;
                ahi[mi][0] = As[base];        ahi[mi][1] = As[base + 160];
                ahi[mi][2] = As[base + 4];    ahi[mi][3] = As[base + 164];
                alo[mi][0] = As[1280 + base];       alo[mi][1] = As[1280 + base + 160];
                alo[mi][2] = As[1280 + base + 4];   alo[mi][3] = As[1280 + base + 164];
            }
            uint32_t bhi[6][2], blo[6][2];
            #pragma unroll
            for (int ni = 0; ni < 6; ni++) {
                int base = (wn + ni*8 + g)*20 + k0 + tg;
                bhi[ni][0] = Bs[base];        bhi[ni][1] = Bs[base + 4];
                blo[ni][0] = Bs[3840 + base]; blo[ni][1] = Bs[3840 + base + 4];
            }
            #pragma unroll
            for (int mi = 0; mi < 2; mi++)
                #pragma unroll
                for (int ni = 0; ni < 6; ni++) {
                    mma_bf16(acc[mi][ni], ahi[mi], bhi[ni]);
                    mma_bf16(acc[mi][ni], ahi[mi], blo[ni]);
                    mma_bf16(acc[mi][ni], alo[mi], bhi[ni]);
                }
        }
    };

    ldgA(0); ldgB(0); stsA(0); stsB(0);
    for (int kc = 0; kc < NC; kc++) {
        if (kc + 1 < NC) { ldgA(kc+1); ldgB(kc+1); }
        __syncthreads();
        compute(kc & 1);
        if (kc + 1 < NC) { stsA((kc+1) & 1); stsB((kc+1) & 1); }
    }

    if (MODE == 0) {
        #pragma unroll
        for (int mi = 0; mi < 2; mi++)
            #pragma unroll
            for (int ni = 0; ni < 6; ni++) {
                int col  = wn + ni*8 + tg*2;
                int row0 = mt*64 + wm + mi*16 + g;
                float b0 = bias[col], b1 = bias[col+1];
                float2 v0 = make_float2(acc[mi][ni][0] + b0, acc[mi][ni][1] + b1);
                float2 v1 = make_float2(acc[mi][ni][2] + b0, acc[mi][ni][3] + b1);
                *reinterpret_cast<float2*>(out + (size_t)row0*256 + col)     = v0;
                *reinterpret_cast<float2*>(out + (size_t)(row0+8)*256 + col) = v1;
            }
    } else {
        #pragma unroll
        for (int mi = 0; mi < 2; mi++)
            #pragma unroll
            for (int ni = 0; ni < 6; ni++) {
                int col = wn + ni*8 + tg*2;
                int row = mt*64 + wm + mi*16 + g;
                qkv_store(row,     col,     acc[mi][ni][0], bias);
                qkv_store(row,     col + 1, acc[mi][ni][1], bias);
                qkv_store(row + 8, col,     acc[mi][ni][2], bias);
                qkv_store(row + 8, col + 1, acc[mi][ni][3], bias);
            }
    }
}

// ================= fused attention v3: branch-free bound-softmax =================
// softmax is invariant to subtracting ANY constant >= row max. Use the cheap
// upper bound M[i] = sum_d |q_d|*colmax_d + max_j rw[i,j] + max_t rh[i,t],
// computed once per block -> inner loop is straight-line (no online max, no
// branch, no rescale, no max-merge in the reduction). All in log2 domain.
// rh stored transposed (rhT[t*32+yq]) -> one broadcast LDS.128 per t per warp.
#define ATTN_SMEM ((4*4096 + 1024 + 1024 + 256) * 4)

__global__ __launch_bounds__(256, 2) void attn_kernel(
    const float* __restrict__ rel_w, const float* __restrict__ rel_h)
{
    extern __shared__ float smf[];
    float4* K0  = reinterpret_cast<float4*>(smf);
    float4* K1  = reinterpret_cast<float4*>(smf + 4096);
    float4* V0  = reinterpret_cast<float4*>(smf + 8192);
    float4* V1  = reinterpret_cast<float4*>(smf + 12288);
    float*  rw  = smf + 16384;          // [yq][yj]
    float*  rhT = smf + 17408;          // [xj][yq]  (transposed!)
    float*  qs  = smf + 18432;          // [yq][d], log2-scaled
    __shared__ float s_colmax[8];
    __shared__ float s_M[32];

    const int tid  = threadIdx.x;
    const int lane = tid & 31;
    const int wrp  = tid >> 5;
    const int blk  = blockIdx.x;
    const int bn   = blk >> 5;
    const int xi   = blk & 31;

    const float4* kg = reinterpret_cast<const float4*>(g_k + bn*SEQ*8);
    const float4* vg = reinterpret_cast<const float4*>(g_v + bn*SEQ*8);
    const float*  qg = g_q + bn*SEQ*8 + xi*32*8;

    // K/V: coalesced LDG.128, scatter into half-arrays
    for (int i = tid; i < 2048; i += 256) {
        float4 kv = kg[i];
        float4 vv = vg[i];
        int j = i >> 1;
        if (i & 1) { K1[j] = kv; V1[j] = vv; }
        else       { K0[j] = kv; V0[j] = vv; }
    }
    qs[tid] = qg[tid] * 1.4426950408889634f;   // log2(e)
    __syncthreads();

    // rel tables (log2 domain since qs is scaled)
    for (int e = tid; e < 1024; e += 256) {
        int yq = e >> 5, yj = e & 31;
        const float* rk = rel_w + (yj - yq + 31)*8;
        float s = 0.f;
        #pragma unroll
        for (int d = 0; d < 8; d++) s = fmaf(qs[yq*8 + d], rk[d], s);
        rw[e] = s;
    }
    for (int e = tid; e < 1024; e += 256) {
        int yq = e & 31, xj = e >> 5;          // e = xj*32 + yq (transposed fill)
        const float* rk = rel_h + (xj - xi + 31)*8;
        float s = 0.f;
        #pragma unroll
        for (int d = 0; d < 8; d++) s = fmaf(qs[yq*8 + d], rk[d], s);
        rhT[e] = s;
    }
    // colmax_d = max_j |K[j][d]|  (warp w handles dim d = w)
    {
        int off = (wrp < 4) ? wrp : (4096 + wrp - 4);
        float mx = 0.f;
        #pragma unroll
        for (int t = 0; t < 32; t++)
            mx = fmaxf(mx, fabsf(smf[off + (t*32 + lane)*4]));
        #pragma unroll
        for (int o = 16; o > 0; o >>= 1)
            mx = fmaxf(mx, __shfl_xor_sync(0xffffffffu, mx, o));
        if (lane == 0) s_colmax[wrp] = mx;
    }
    __syncthreads();

    // per-query upper bound M[yq]
    if (tid < 32) {
        int yq = tid;
        float mrw = -1e30f, mrh = -1e30f;
        #pragma unroll
        for (int t = 0; t < 32; t++) {
            mrw = fmaxf(mrw, rw[yq*32 + t]);
            mrh = fmaxf(mrh, rhT[t*32 + yq]);
        }
        float dot = 0.f;
        #pragma unroll
        for (int d = 0; d < 8; d++)
            dot = fmaf(fabsf(qs[yq*8 + d]), s_colmax[d], dot);
        s_M[yq] = dot + mrw + mrh;
    }
    __syncthreads();

    const int w4 = wrp * 4;
    float qv[4][8];
    float rwm[4];                               // rw - M, loop invariant
    #pragma unroll
    for (int qi = 0; qi < 4; qi++) {
        rwm[qi] = rw[(w4 + qi)*32 + lane] - s_M[w4 + qi];
        #pragma unroll
        for (int d = 0; d < 8; d++) qv[qi][d] = qs[(w4 + qi)*8 + d];
    }

    float ssum[4] = {0.f, 0.f, 0.f, 0.f};
    float acc[4][8];
    #pragma unroll
    for (int qi = 0; qi < 4; qi++)
        #pragma unroll
        for (int d = 0; d < 8; d++) acc[qi][d] = 0.f;

    // straight-line single pass: exp2(logit - M), no max tracking
    for (int t = 0; t < 32; t++) {
        const int j = t*32 + lane;
        const float4 k0 = K0[j], k1 = K1[j];
        const float4 v0 = V0[j], v1 = V1[j];
        const float4 rh4 = *reinterpret_cast<const float4*>(&rhT[t*32 + w4]);
        const float rr[4] = {rh4.x, rh4.y, rh4.z, rh4.w};
        #pragma unroll
        for (int qi = 0; qi < 4; qi++) {
            float lgA = fmaf(qv[qi][0], k0.x, rwm[qi]);
            lgA = fmaf(qv[qi][1], k0.y, lgA);
            lgA = fmaf(qv[qi][2], k0.z, lgA);
            lgA = fmaf(qv[qi][3], k0.w, lgA);
            float lgB = fmaf(qv[qi][4], k1.x, rr[qi]);
            lgB = fmaf(qv[qi][5], k1.y, lgB);
            lgB = fmaf(qv[qi][6], k1.z, lgB);
            lgB = fmaf(qv[qi][7], k1.w, lgB);
            float p = ex2f(lgA + lgB);
            ssum[qi] += p;
            acc[qi][0] = fmaf(p, v0.x, acc[qi][0]);
            acc[qi][1] = fmaf(p, v0.y, acc[qi][1]);
            acc[qi][2] = fmaf(p, v0.z, acc[qi][2]);
            acc[qi][3] = fmaf(p, v0.w, acc[qi][3]);
            acc[qi][4] = fmaf(p, v1.x, acc[qi][4]);
            acc[qi][5] = fmaf(p, v1.y, acc[qi][5]);
            acc[qi][6] = fmaf(p, v1.z, acc[qi][6]);
            acc[qi][7] = fmaf(p, v1.w, acc[qi][7]);
        }
    }

    // butterfly allreduce (sum only — no max merging needed)
    #pragma unroll
    for (int off = 16; off > 0; off >>= 1) {
        #pragma unroll
        for (int qi = 0; qi < 4; qi++) {
            ssum[qi] += __shfl_xor_sync(0xffffffffu, ssum[qi], off);
            #pragma unroll
            for (int d = 0; d < 8; d++)
                acc[qi][d] += __shfl_xor_sync(0xffffffffu, acc[qi][d], off);
        }
    }

    __syncthreads();
    if (lane == 0) {
        #pragma unroll
        for (int qi = 0; qi < 4; qi++) {
            float inv = 1.f / ssum[qi];
            #pragma unroll
            for (int d = 0; d < 8; d++) qs[(w4 + qi)*8 + d] = acc[qi][d] * inv;
        }
    }
    __syncthreads();
    {
        int b = bn >> 3, n = bn & 7;
        int yq = tid >> 3, d = tid & 7;
        g_attn[(b*SEQ + xi*32 + yq)*64 + n*8 + d] = qs[tid];
    }
}

// ================= output projection (512 blocks, 16 rows each) =================
__global__ __launch_bounds__(256) void proj_kernel(
    const float* __restrict__ w, const float* __restrict__ bias,
    float* __restrict__ out)
{
    __shared__ float at[16][64];
    __shared__ float ws[64][64];
    const int tid = threadIdx.x;
    const int p0  = blockIdx.x * 16;

    for (int i = tid; i < 16*64; i += 256) at[i >> 6][i & 63] = g_attn[p0*64 + i];
    for (int i = tid; i < 64*64; i += 256) ws[i >> 6][i & 63] = w[i];
    __syncthreads();

    const int o  = tid & 63;
    const int pg = tid >> 6;
    float acc[4];
    #pragma unroll
    for (int i = 0; i < 4; i++) acc[i] = 0.f;

    #pragma unroll
    for (int c = 0; c < 64; c++) {
        float wv = ws[c][o];
        #pragma unroll
        for (int i = 0; i < 4; i++)
            acc[i] = fmaf(at[pg + 4*i][c], wv, acc[i]);
    }
    float bb = bias[o];
    #pragma unroll
    for (int i = 0; i < 4; i++)
        out[(p0 + pg + 4*i)*256 + 192 + o] = acc[i] + bb;
}

// ================= launch =================
extern "C" void kernel_launch(void* const* d_in, const int* in_sizes, int n_in,
                              void* d_out, int out_size)
{
    const float* x       = (const float*)d_in[0];
    const float* conv_w  = (const float*)d_in[1];
    const float* conv_b  = (const float*)d_in[2];
    const float* qkv_w   = (const float*)d_in[3];
    const float* qkv_b   = (const float*)d_in[4];
    const float* attn_w  = (const float*)d_in[5];
    const float* attn_b  = (const float*)d_in[6];
    const float* relw    = (const float*)d_in[7];
    const float* relh    = (const float*)d_in[8];
    float* out = (float*)d_out;

    __nv_bfloat16 *bhi, *blo, *qbhi, *qblo;
    cudaGetSymbolAddress((void**)&bhi,  g_Bhi);
    cudaGetSymbolAddress((void**)&blo,  g_Blo);
    cudaGetSymbolAddress((void**)&qbhi, g_QBhi);
    cudaGetSymbolAddress((void**)&qblo, g_QBlo);

    cudaFuncSetAttribute(attn_kernel, cudaFuncAttributeMaxDynamicSharedMemorySize, ATTN_SMEM);
    cudaFuncSetAttribute(gemm_kernel<0>, cudaFuncAttributeMaxDynamicSharedMemorySize, GEMM_SMEM);
    cudaFuncSetAttribute(gemm_kernel<1>, cudaFuncAttributeMaxDynamicSharedMemorySize, GEMM_SMEM);

    bprep_kernel<<<(192*2304 + 192*256 + 255)/256, 256>>>(conv_w, qkv_w);
    gemm_kernel<1><<<128, 256, GEMM_SMEM>>>(x, qbhi, qblo, qkv_b, nullptr);
    gemm_kernel<0><<<128, 256, GEMM_SMEM>>>(x, bhi, blo, conv_b, out);
    attn_kernel<<<NB*NHEAD*HH, 256, ATTN_SMEM>>>(relw, relh);
    proj_kernel<<<NB*SEQ/16, 256>>>(attn_w, attn_b, out);
}

// round 17
// speedup vs baseline: 1.1143x; 1.0158x over previous
#include <cuda_runtime.h>
#include <cuda_bf16.h>
#include <math.h>
#include <stdint.h>

#define NB    8
#define HH    32
#define WW    32
#define CINC  256
#define NHEAD 8
#define SEQ   1024

typedef unsigned long long u64;

// ---------------- scratch (static device globals; no allocation) ----------------
__device__ float g_q[NB*NHEAD*SEQ*8];
__device__ float g_k[NB*NHEAD*SEQ*8];
__device__ float g_v[NB*NHEAD*SEQ*8];
__device__ float g_attn[NB*SEQ*64];

// split-bf16 transposed weights: conv B (192 x 2304), qkv B (192 x 256)
__device__ __align__(16) __nv_bfloat16 g_Bhi[192*2304];
__device__ __align__(16) __nv_bfloat16 g_Blo[192*2304];
__device__ __align__(16) __nv_bfloat16 g_QBhi[192*256];
__device__ __align__(16) __nv_bfloat16 g_QBlo[192*256];

__device__ __forceinline__ float ex2f(float x) {
    float y;
    asm("ex2.approx.f32 %0, %1;" : "=f"(y) : "f"(x));
    return y;
}

// ---------------- packed f32x2 helpers (sm_100+ base ISA, no 'a' suffix) ----------
__device__ __forceinline__ u64 pk2(float lo, float hi) {
    u64 r;
    asm("mov.b64 %0, {%1, %2};" : "=l"(r) : "r"(__float_as_uint(lo)), "r"(__float_as_uint(hi)));
    return r;
}
__device__ __forceinline__ void upk2(float& lo, float& hi, u64 v) {
    uint32_t a, b;
    asm("mov.b64 {%0, %1}, %2;" : "=r"(a), "=r"(b) : "l"(v));
    lo = __uint_as_float(a); hi = __uint_as_float(b);
}
__device__ __forceinline__ u64 fma2(u64 a, u64 b, u64 c) {
    u64 d;
    asm("fma.rn.f32x2 %0, %1, %2, %3;" : "=l"(d) : "l"(a), "l"(b), "l"(c));
    return d;
}
__device__ __forceinline__ u64 mul2(u64 a, u64 b) {
    u64 d;
    asm("mul.rn.f32x2 %0, %1, %2;" : "=l"(d) : "l"(a), "l"(b));
    return d;
}
__device__ __forceinline__ u64 add2(u64 a, u64 b) {
    u64 d;
    asm("add.rn.f32x2 %0, %1, %2;" : "=l"(d) : "l"(a), "l"(b));
    return d;
}

// ================= warp-level bf16 MMA =================
__device__ __forceinline__ void mma_bf16(float* c, const uint32_t* a, const uint32_t* b)
{
    asm volatile(
        "mma.sync.aligned.m16n8k16.row.col.f32.bf16.bf16.f32 "
        "{%0,%1,%2,%3}, {%4,%5,%6,%7}, {%8,%9}, {%0,%1,%2,%3};\n"
        : "+f"(c[0]), "+f"(c[1]), "+f"(c[2]), "+f"(c[3])
        : "r"(a[0]), "r"(a[1]), "r"(a[2]), "r"(a[3]),
          "r"(b[0]), "r"(b[1]));
}

// ================= weight prep: transpose + hi/lo split =================
__global__ __launch_bounds__(256) void bprep_kernel(
    const float* __restrict__ conv_w, const float* __restrict__ qkv_w)
{
    int idx = blockIdx.x * 256 + threadIdx.x;
    if (idx < 192*2304) {
        int n = idx / 2304, k = idx - n*2304;
        float v = conv_w[k*192 + n];
        __nv_bfloat16 h = __float2bfloat16(v);
        g_Bhi[idx] = h;
        g_Blo[idx] = __float2bfloat16(v - __bfloat162float(h));
    } else {
        int j = idx - 192*2304;
        if (j < 192*256) {
            int n = j / 256, k = j - n*256;
            float v = qkv_w[k*192 + n];
            __nv_bfloat16 h = __float2bfloat16(v);
            g_QBhi[j] = h;
            g_QBlo[j] = __float2bfloat16(v - __bfloat162float(h));
        }
    }
}

// ================= qkv scatter helper =================
__device__ __forceinline__ void qkv_store(int row, int col, float v, const float* bias)
{
    v += bias[col];
    int b = row >> 10, s = row & 1023;
    if (col < 64) {
        g_k[((b*8 + (col >> 3))*SEQ + s)*8 + (col & 7)] = v;
    } else if (col < 128) {
        int o = col - 64;
        g_q[((b*8 + (o >> 3))*SEQ + s)*8 + (o & 7)] = v * 0.35355339059327373f;
    } else {
        int o = col - 128;
        g_v[((b*8 + (o >> 3))*SEQ + s)*8 + (o & 7)] = v;
    }
}

// ================= unified split-bf16 GEMM (MODE 0 = conv-im2col, MODE 1 = qkv) =====
#define STG_ELEMS 20480
#define GEMM_SMEM (2*STG_ELEMS*2)

template<int MODE>
__global__ __launch_bounds__(256, 1) void gemm_kernel(
    const float* __restrict__ x,
    const __nv_bfloat16* __restrict__ Bhi,
    const __nv_bfloat16* __restrict__ Blo,
    const float* __restrict__ bias,
    float* __restrict__ out)
{
    constexpr int NC = MODE ? 8 : 72;
    constexpr int KB = MODE ? 256 : 2304;

    extern __shared__ __align__(16) __nv_bfloat16 sm[];

    const int tid  = threadIdx.x;
    const int lane = tid & 31;
    const int wid  = tid >> 5;
    const int mt   = blockIdx.x;

    const int ar  = tid >> 2;
    const int acg = (tid & 3) * 8;
    const int p   = mt*64 + ar;
    const int pb  = p >> 10, py = (p >> 5) & 31, px = p & 31;

    float aregs[8];
    uint4 bregs[6];

    const int wm = (wid >> 2) * 32;
    const int wn = (wid & 3) * 48;
    const int g  = lane >> 2;
    const int tg = lane & 3;

    float acc[2][6][4];
    #pragma unroll
    for (int mi = 0; mi < 2; mi++)
        #pragma unroll
        for (int ni = 0; ni < 6; ni++)
            #pragma unroll
            for (int e = 0; e < 4; e++) acc[mi][ni][e] = 0.f;

    auto ldgA = [&](int kc) {
        int dy, dx, c0;
        if (MODE) { dy = 0; dx = 0; c0 = kc * 32; }
        else { int t = kc >> 3; dy = t/3 - 1; dx = t%3 - 1; c0 = (kc & 7) * 32; }
        int yy = py + dy, xx = px + dx;
        bool valid = MODE ? true : ((unsigned)yy < 32u && (unsigned)xx < 32u);
        if (valid) {
            const float4* s = reinterpret_cast<const float4*>(
                x + ((size_t)(pb*1024 + yy*32 + xx))*256 + c0 + acg);
            float4 v0 = s[0], v1 = s[1];
            aregs[0]=v0.x; aregs[1]=v0.y; aregs[2]=v0.z; aregs[3]=v0.w;
            aregs[4]=v1.x; aregs[5]=v1.y; aregs[6]=v1.z; aregs[7]=v1.w;
        } else {
            #pragma unroll
            for (int i = 0; i < 8; i++) aregs[i] = 0.f;
        }
    };

    auto ldgB = [&](int kc) {
        const int kbase = kc * 32;
        #pragma unroll
        for (int i = 0; i < 6; i++) {
            int idx  = tid + i*256;
            int half = idx >= 768;
            int j    = idx - half*768;
            int n    = j >> 2, gg = (j & 3) * 8;
            const __nv_bfloat16* src = (half ? Blo : Bhi) + (size_t)n*KB + kbase + gg;
            bregs[i] = *reinterpret_cast<const uint4*>(src);
        }
    };

    auto stsA = [&](int st) {
        __nv_bfloat16* As = sm + st*STG_ELEMS;
        __nv_bfloat162 h[4], l[4];
        #pragma unroll
        for (int i = 0; i < 4; i++) {
            float v0 = aregs[2*i], v1 = aregs[2*i+1];
            __nv_bfloat16 h0 = __float2bfloat16(v0), h1 = __float2bfloat16(v1);
            h[i].x = h0; h[i].y = h1;
            l[i].x = __float2bfloat16(v0 - __bfloat162float(h0));
            l[i].y = __float2bfloat16(v1 - __bfloat162float(h1));
        }
        *reinterpret_cast<uint4*>(As + ar*40 + acg)        = *reinterpret_cast<uint4*>(h);
        *reinterpret_cast<uint4*>(As + 2560 + ar*40 + acg) = *reinterpret_cast<uint4*>(l);
    };

    auto stsB = [&](int st) {
        __nv_bfloat16* Bs = sm + st*STG_ELEMS + 5120;
        #pragma unroll
        for (int i = 0; i < 6; i++) {
            int idx  = tid + i*256;
            int half = idx >= 768;
            int j    = idx - half*768;
            int n    = j >> 2, gg = (j & 3) * 8;
            *reinterpret_cast<uint4*>(Bs + half*7680 + n*40 + gg) = bregs[i];
        }
    };

    auto compute = [&](int st) {
        const uint32_t* As = reinterpret_cast<const uint32_t*>(sm + st*STG_ELEMS);
        const uint32_t* Bs = reinterpret_cast<const uint32_t*>(sm + st*STG_ELEMS + 5120);
        #pragma unroll
        for (int ks = 0; ks < 2; ks++) {
            const int k0 = ks * 8;
            uint32_t ahi[2][4], alo[2][4];
            #pragma unroll
            for (int mi = 0; mi < 2; mi++) {
                int base = (wm + mi*16 + g)*20 + k0 + tg;
                ahi[mi][0] = As[base];        ahi[mi][1] = As[base + 160];
                ahi[mi][2] = As[base + 4];    ahi[mi][3] = As[base + 164];
                alo[mi][0] = As[1280 + base];       alo[mi][1] = As[1280 + base + 160];
                alo[mi][2] = As[1280 + base + 4];   alo[mi][3] = As[1280 + base + 164];
            }
            uint32_t bhi[6][2], blo[6][2];
            #pragma unroll
            for (int ni = 0; ni < 6; ni++) {
                int base = (wn + ni*8 + g)*20 + k0 + tg;
                bhi[ni][0] = Bs[base];        bhi[ni][1] = Bs[base + 4];
                blo[ni][0] = Bs[3840 + base]; blo[ni][1] = Bs[3840 + base + 4];
            }
            #pragma unroll
            for (int mi = 0; mi < 2; mi++)
                #pragma unroll
                for (int ni = 0; ni < 6; ni++) {
                    mma_bf16(acc[mi][ni], ahi[mi], bhi[ni]);
                    mma_bf16(acc[mi][ni], ahi[mi], blo[ni]);
                    mma_bf16(acc[mi][ni], alo[mi], bhi[ni]);
                }
        }
    };

    ldgA(0); ldgB(0); stsA(0); stsB(0);
    for (int kc = 0; kc < NC; kc++) {
        if (kc + 1 < NC) { ldgA(kc+1); ldgB(kc+1); }
        __syncthreads();
        compute(kc & 1);
        if (kc + 1 < NC) { stsA((kc+1) & 1); stsB((kc+1) & 1); }
    }

    if (MODE == 0) {
        #pragma unroll
        for (int mi = 0; mi < 2; mi++)
            #pragma unroll
            for (int ni = 0; ni < 6; ni++) {
                int col  = wn + ni*8 + tg*2;
                int row0 = mt*64 + wm + mi*16 + g;
                float b0 = bias[col], b1 = bias[col+1];
                float2 v0 = make_float2(acc[mi][ni][0] + b0, acc[mi][ni][1] + b1);
                float2 v1 = make_float2(acc[mi][ni][2] + b0, acc[mi][ni][3] + b1);
                *reinterpret_cast<float2*>(out + (size_t)row0*256 + col)     = v0;
                *reinterpret_cast<float2*>(out + (size_t)(row0+8)*256 + col) = v1;
            }
    } else {
        #pragma unroll
        for (int mi = 0; mi < 2; mi++)
            #pragma unroll
            for (int ni = 0; ni < 6; ni++) {
                int col = wn + ni*8 + tg*2;
                int row = mt*64 + wm + mi*16 + g;
                qkv_store(row,     col,     acc[mi][ni][0], bias);
                qkv_store(row,     col + 1, acc[mi][ni][1], bias);
                qkv_store(row + 8, col,     acc[mi][ni][2], bias);
                qkv_store(row + 8, col + 1, acc[mi][ni][3], bias);
            }
    }
}

// ================= fused attention v4: 64 queries/block + packed f32x2 ============
// block = (b, n, xi-pair): TWO xi columns (64 queries) share one K/V smem image.
// Warp w owns yq in [4w,4w+4) for BOTH columns; the (xi_a, xi_b) query pair is
// packed into one f32x2 lane -> 8 packed FMA give both logits; PV packed over d.
// Branch-free bound-softmax (log2 domain) as v3. rw padded to stride 33 (kills
// the 32-way conflict in the M loop).
//
// smem floats: K0 0, K1 4096, V0 8192, V1 12288,
//   rwa 16384 (32x33=1056), rwb 17440 (1056),
//   rhTa 18496 (1024, [xj][yq]), rhTb 19520 (1024),
//   qsa 20544 (256), qsb 20800 (256)    -> total 21056 floats
#define ATTN_SMEM (21056 * 4)

__global__ __launch_bounds__(256, 1) void attn_kernel(
    const float* __restrict__ rel_w, const float* __restrict__ rel_h)
{
    extern __shared__ float smf[];
    float4* K0  = reinterpret_cast<float4*>(smf);
    float4* K1  = reinterpret_cast<float4*>(smf + 4096);
    float4* V0  = reinterpret_cast<float4*>(smf + 8192);
    float4* V1  = reinterpret_cast<float4*>(smf + 12288);
    float*  rwa  = smf + 16384;
    float*  rwb  = smf + 17440;
    float*  rhTa = smf + 18496;
    float*  rhTb = smf + 19520;
    float*  qsa  = smf + 20544;
    float*  qsb  = smf + 20800;
    __shared__ float s_colmax[8];
    __shared__ float s_M[2][32];

    const int tid  = threadIdx.x;
    const int lane = tid & 31;
    const int wrp  = tid >> 5;
    const int blk  = blockIdx.x;
    const int bn   = blk >> 4;           // 0..63
    const int xp   = blk & 15;
    const int xia  = xp*2, xib = xp*2 + 1;

    const float4* kg = reinterpret_cast<const float4*>(g_k + bn*SEQ*8);
    const float4* vg = reinterpret_cast<const float4*>(g_v + bn*SEQ*8);
    const float*  qga = g_q + bn*SEQ*8 + xia*32*8;
    const float*  qgb = g_q + bn*SEQ*8 + xib*32*8;

    for (int i = tid; i < 2048; i += 256) {
        float4 kv = kg[i];
        float4 vv = vg[i];
        int j = i >> 1;
        if (i & 1) { K1[j] = kv; V1[j] = vv; }
        else       { K0[j] = kv; V0[j] = vv; }
    }
    qsa[tid] = qga[tid] * 1.4426950408889634f;
    qsb[tid] = qgb[tid] * 1.4426950408889634f;
    __syncthreads();

    // rel tables (log2 domain), per xi column
    for (int e = tid; e < 1024; e += 256) {
        int yq = e >> 5, yj = e & 31;
        const float* rk = rel_w + (yj - yq + 31)*8;
        float sa = 0.f, sb = 0.f;
        #pragma unroll
        for (int d = 0; d < 8; d++) {
            float r = rk[d];
            sa = fmaf(qsa[yq*8 + d], r, sa);
            sb = fmaf(qsb[yq*8 + d], r, sb);
        }
        rwa[yq*33 + yj] = sa;
        rwb[yq*33 + yj] = sb;
    }
    for (int e = tid; e < 1024; e += 256) {
        int yq = e & 31, xj = e >> 5;
        const float* rka = rel_h + (xj - xia + 31)*8;
        const float* rkb = rel_h + (xj - xib + 31)*8;
        float sa = 0.f, sb = 0.f;
        #pragma unroll
        for (int d = 0; d < 8; d++) {
            sa = fmaf(qsa[yq*8 + d], rka[d], sa);
            sb = fmaf(qsb[yq*8 + d], rkb[d], sb);
        }
        rhTa[xj*32 + yq] = sa;
        rhTb[xj*32 + yq] = sb;
    }
    // colmax_d = max_j |K[j][d]| (warp w handles dim d = w)
    {
        int base = ((wrp < 4) ? 0 : 4096) + (wrp & 3);
        float mx = 0.f;
        #pragma unroll
        for (int t = 0; t < 32; t++)
            mx = fmaxf(mx, fabsf(smf[base + (t*32 + lane)*4]));
        #pragma unroll
        for (int o = 16; o > 0; o >>= 1)
            mx = fmaxf(mx, __shfl_xor_sync(0xffffffffu, mx, o));
        if (lane == 0) s_colmax[wrp] = mx;
    }
    __syncthreads();

    // per-query upper bound M[xi][yq] (stride-33 rw -> conflict-free)
    if (tid < 64) {
        int sel = tid >> 5, yq = tid & 31;
        const float* rwp = sel ? rwb : rwa;
        const float* rhp = sel ? rhTb : rhTa;
        const float* qsp = sel ? qsb : qsa;
        float mrw = -1e30f, mrh = -1e30f;
        #pragma unroll
        for (int t = 0; t < 32; t++) {
            mrw = fmaxf(mrw, rwp[yq*33 + t]);
            mrh = fmaxf(mrh, rhp[t*32 + yq]);
        }
        float dot = 0.f;
        #pragma unroll
        for (int d = 0; d < 8; d++)
            dot = fmaf(fabsf(qsp[yq*8 + d]), s_colmax[d], dot);
        s_M[sel][yq] = dot + mrw + mrh;
    }
    __syncthreads();

    const int w4 = wrp * 4;
    u64 qp[4][8];    // pack(q_a, q_b) per (yq, d)
    u64 rwmp[4];     // pack(rwa - Ma, rwb - Mb) per yq at yj=lane
    #pragma unroll
    for (int qi = 0; qi < 4; qi++) {
        int yq = w4 + qi;
        rwmp[qi] = pk2(rwa[yq*33 + lane] - s_M[0][yq],
                       rwb[yq*33 + lane] - s_M[1][yq]);
        #pragma unroll
        for (int d = 0; d < 8; d++)
            qp[qi][d] = pk2(qsa[yq*8 + d], qsb[yq*8 + d]);
    }

    u64 ssp[4]     = {0, 0, 0, 0};
    u64 acca[4][4] = {};
    u64 accb[4][4] = {};

    for (int t = 0; t < 32; t++) {
        const int j = t*32 + lane;
        const float4 k0 = K0[j], k1 = K1[j];
        const float4 v0 = V0[j], v1 = V1[j];
        u64 kp[8];
        kp[0] = pk2(k0.x, k0.x); kp[1] = pk2(k0.y, k0.y);
        kp[2] = pk2(k0.z, k0.z); kp[3] = pk2(k0.w, k0.w);
        kp[4] = pk2(k1.x, k1.x); kp[5] = pk2(k1.y, k1.y);
        kp[6] = pk2(k1.z, k1.z); kp[7] = pk2(k1.w, k1.w);
        u64 vp[4];
        vp[0] = pk2(v0.x, v0.y); vp[1] = pk2(v0.z, v0.w);
        vp[2] = pk2(v1.x, v1.y); vp[3] = pk2(v1.z, v1.w);
        const float4 ra = *reinterpret_cast<const float4*>(&rhTa[t*32 + w4]);
        const float4 rb = *reinterpret_cast<const float4*>(&rhTb[t*32 + w4]);
        const float raa[4] = {ra.x, ra.y, ra.z, ra.w};
        const float rbb[4] = {rb.x, rb.y, rb.z, rb.w};
        #pragma unroll
        for (int qi = 0; qi < 4; qi++) {
            u64 lgA = add2(rwmp[qi], pk2(raa[qi], rbb[qi]));
            lgA = fma2(qp[qi][0], kp[0], lgA);
            lgA = fma2(qp[qi][1], kp[1], lgA);
            lgA = fma2(qp[qi][2], kp[2], lgA);
            lgA = fma2(qp[qi][3], kp[3], lgA);
            u64 lgB = mul2(qp[qi][4], kp[4]);
            lgB = fma2(qp[qi][5], kp[5], lgB);
            lgB = fma2(qp[qi][6], kp[6], lgB);
            lgB = fma2(qp[qi][7], kp[7], lgB);
            float la, lb;
            upk2(la, lb, add2(lgA, lgB));
            float pa = ex2f(la);
            float pb = ex2f(lb);
            ssp[qi] = add2(ssp[qi], pk2(pa, pb));
            u64 pap = pk2(pa, pa), pbp = pk2(pb, pb);
            acca[qi][0] = fma2(pap, vp[0], acca[qi][0]);
            acca[qi][1] = fma2(pap, vp[1], acca[qi][1]);
            acca[qi][2] = fma2(pap, vp[2], acca[qi][2]);
            acca[qi][3] = fma2(pap, vp[3], acca[qi][3]);
            accb[qi][0] = fma2(pbp, vp[0], accb[qi][0]);
            accb[qi][1] = fma2(pbp, vp[1], accb[qi][1]);
            accb[qi][2] = fma2(pbp, vp[2], accb[qi][2]);
            accb[qi][3] = fma2(pbp, vp[3], accb[qi][3]);
        }
    }

    // butterfly allreduce (packed adds; sum only)
    #pragma unroll
    for (int off = 16; off > 0; off >>= 1) {
        #pragma unroll
        for (int qi = 0; qi < 4; qi++) {
            ssp[qi] = add2(ssp[qi], __shfl_xor_sync(0xffffffffu, ssp[qi], off));
            #pragma unroll
            for (int e = 0; e < 4; e++) {
                acca[qi][e] = add2(acca[qi][e], __shfl_xor_sync(0xffffffffu, acca[qi][e], off));
                accb[qi][e] = add2(accb[qi][e], __shfl_xor_sync(0xffffffffu, accb[qi][e], off));
            }
        }
    }

    __syncthreads();   // all qs/rw/rh reads complete; reuse qsa..qsb as staging (512 f)
    float* so = qsa;
    if (lane == 0) {
        #pragma unroll
        for (int qi = 0; qi < 4; qi++) {
            float sa, sb;
            upk2(sa, sb, ssp[qi]);
            float ia = 1.f / sa, ib = 1.f / sb;
            #pragma unroll
            for (int e = 0; e < 4; e++) {
                float xa, ya, xb, yb;
                upk2(xa, ya, acca[qi][e]);
                upk2(xb, yb, accb[qi][e]);
                so[(w4 + qi)*8 + 2*e]          = xa * ia;
                so[(w4 + qi)*8 + 2*e + 1]      = ya * ia;
                so[(32 + w4 + qi)*8 + 2*e]     = xb * ib;
                so[(32 + w4 + qi)*8 + 2*e + 1] = yb * ib;
            }
        }
    }
    __syncthreads();
    {
        int b = bn >> 3, n = bn & 7;
        #pragma unroll
        for (int i = tid; i < 512; i += 256) {
            int q = i >> 3, d = i & 7;
            int xi = xia + (q >> 5), yq = q & 31;
            g_attn[(b*SEQ + xi*32 + yq)*64 + n*8 + d] = so[i];
        }
    }
}

// ================= output projection (512 blocks, 16 rows each) =================
__global__ __launch_bounds__(256) void proj_kernel(
    const float* __restrict__ w, const float* __restrict__ bias,
    float* __restrict__ out)
{
    __shared__ float at[16][64];
    __shared__ float ws[64][64];
    const int tid = threadIdx.x;
    const int p0  = blockIdx.x * 16;

    for (int i = tid; i < 16*64; i += 256) at[i >> 6][i & 63] = g_attn[p0*64 + i];
    for (int i = tid; i < 64*64; i += 256) ws[i >> 6][i & 63] = w[i];
    __syncthreads();

    const int o  = tid & 63;
    const int pg = tid >> 6;
    float acc[4];
    #pragma unroll
    for (int i = 0; i < 4; i++) acc[i] = 0.f;

    #pragma unroll
    for (int c = 0; c < 64; c++) {
        float wv = ws[c][o];
        #pragma unroll
        for (int i = 0; i < 4; i++)
            acc[i] = fmaf(at[pg + 4*i][c], wv, acc[i]);
    }
    float bb = bias[o];
    #pragma unroll
    for (int i = 0; i < 4; i++)
        out[(p0 + pg + 4*i)*256 + 192 + o] = acc[i] + bb;
}

// ================= launch =================
extern "C" void kernel_launch(void* const* d_in, const int* in_sizes, int n_in,
                              void* d_out, int out_size)
{
    const float* x       = (const float*)d_in[0];
    const float* conv_w  = (const float*)d_in[1];
    const float* conv_b  = (const float*)d_in[2];
    const float* qkv_w   = (const float*)d_in[3];
    const float* qkv_b   = (const float*)d_in[4];
    const float* attn_w  = (const float*)d_in[5];
    const float* attn_b  = (const float*)d_in[6];
    const float* relw    = (const float*)d_in[7];
    const float* relh    = (const float*)d_in[8];
    float* out = (float*)d_out;

    __nv_bfloat16 *bhi, *blo, *qbhi, *qblo;
    cudaGetSymbolAddress((void**)&bhi,  g_Bhi);
    cudaGetSymbolAddress((void**)&blo,  g_Blo);
    cudaGetSymbolAddress((void**)&qbhi, g_QBhi);
    cudaGetSymbolAddress((void**)&qblo, g_QBlo);

    cudaFuncSetAttribute(attn_kernel, cudaFuncAttributeMaxDynamicSharedMemorySize, ATTN_SMEM);
    cudaFuncSetAttribute(gemm_kernel<0>, cudaFuncAttributeMaxDynamicSharedMemorySize, GEMM_SMEM);
    cudaFuncSetAttribute(gemm_kernel<1>, cudaFuncAttributeMaxDynamicSharedMemorySize, GEMM_SMEM);

    bprep_kernel<<<(192*2304 + 192*256 + 255)/256, 256>>>(conv_w, qkv_w);
    gemm_kernel<1><<<128, 256, GEMM_SMEM>>>(x, qbhi, qblo, qkv_b, nullptr);
    gemm_kernel<0><<<128, 256, GEMM_SMEM>>>(x, bhi, blo, conv_b, out);
    attn_kernel<<<64*16, 256, ATTN_SMEM>>>(relw, relh);
    proj_kernel<<<NB*SEQ/16, 256>>>(attn_w, attn_b, out);
}